// round 15
// baseline (speedup 1.0000x reference)
#include <cuda_runtime.h>
#include <cuda_fp16.h>

// Problem dims (fixed by the dataset; runtime values derived from in_sizes).
#define NMAX 50000
#define EMAX 800000

// ---- scratch (device globals; no allocation allowed) ----
__device__ float   g_q[NMAX * 128];
__device__ __half2 g_kv[NMAX * 128];   // element j = {k[n,j], v[n,j]} fp16
__device__ float   g_G[NMAX * 64];     // G[n,h*16+i] = sum_d We[i,h*32+d] * q[n,h*32+d]
__device__ float   g_h1[NMAX * 32];    // layer-1 output (skip + attention)
__device__ float   g_h2[NMAX * 32];    // layer-2 output
__device__ float   g_us[NMAX * 32];    // relu(h2) @ Wm1[0:32]
__device__ float   g_ud[NMAX * 32];    // relu(h2) @ Wm1[48:80]
__device__ float   g_easorted[EMAX * 16];  // ea rows permuted into dst-sorted order

// ---- CSR (dst-sorted edges), built once per launch ----
__device__ int g_deg[NMAX];
__device__ int g_rowptr[NMAX + 1];
__device__ int g_cursor[NMAX];
__device__ int g_srcsorted[EMAX];
__device__ int g_eidsorted[EMAX];

// ===========================================================================
// CSR build: (deg zeroed inside node_linear) -> histogram -> single-block
// scan -> scatter -> ea permute
// ===========================================================================
__global__ void csr_hist_kernel(const int* __restrict__ ei, int E) {
    int e = blockIdx.x * blockDim.x + threadIdx.x;
    if (e < E) atomicAdd(&g_deg[ei[E + e]], 1);
}

// Single-block exclusive scan over g_deg -> g_rowptr / g_cursor.
__global__ void csr_scan_kernel(int N) {
    __shared__ int warpsums[32];
    __shared__ int s_carry;
    int tid = threadIdx.x;
    int lane = tid & 31;
    int w = tid >> 5;
    if (tid == 0) s_carry = 0;
    __syncthreads();

    for (int base = 0; base < N; base += 1024) {
        int i = base + tid;
        int v = (i < N) ? g_deg[i] : 0;
        int x = v;
#pragma unroll
        for (int off = 1; off < 32; off <<= 1) {
            int t = __shfl_up_sync(0xffffffffu, x, off);
            if (lane >= off) x += t;
        }
        if (lane == 31) warpsums[w] = x;
        __syncthreads();
        if (w == 0) {
            int y = warpsums[lane];
#pragma unroll
            for (int off = 1; off < 32; off <<= 1) {
                int t = __shfl_up_sync(0xffffffffu, y, off);
                if (lane >= off) y += t;
            }
            warpsums[lane] = y;
        }
        __syncthreads();
        int incl = x + (w ? warpsums[w - 1] : 0) + s_carry;
        if (i < N) {
            g_rowptr[i + 1] = incl;
            g_cursor[i] = incl - v;
        }
        __syncthreads();               // everyone has read s_carry
        if (tid == 1023) s_carry = incl;
        __syncthreads();
    }
    if (tid == 0) g_rowptr[0] = 0;
}

__global__ void csr_scatter_kernel(const int* __restrict__ ei, int E) {
    int e = blockIdx.x * blockDim.x + threadIdx.x;
    if (e >= E) return;
    int src = ei[e];
    int dst = ei[E + e];
    int p = atomicAdd(&g_cursor[dst], 1);
    g_srcsorted[p] = src;
    g_eidsorted[p] = e;
}

// Permute ea rows into sorted order: 16 threads per row, coalesced writes.
__global__ void ea_sort_kernel(const float* __restrict__ ea, int E) {
    int idx = blockIdx.x * blockDim.x + threadIdx.x;
    int p = idx >> 4;
    int i = idx & 15;
    if (p < E)
        g_easorted[idx] = ea[(size_t)g_eidsorted[p] * 16 + i];
}

// ===========================================================================
// Node linears: q = x@Wq+b ([N,128]); k,v packed as half2 {k_j, v_j} in g_kv;
// skip = x@Ws+bs ([N,32]) into outbuf;
// G[n, w*16+i] = sum_d We[i, w*32+d] * q[n, w*32+d]  (warp w = head).
// One block per node, 128 threads. Layer 0 also zeroes g_deg.
// ===========================================================================
__global__ void node_linear_kernel(
    const float* __restrict__ xin, int layer,
    const float* __restrict__ Wq, const float* __restrict__ bq,
    const float* __restrict__ Wk, const float* __restrict__ bk,
    const float* __restrict__ Wv, const float* __restrict__ bv,
    const float* __restrict__ Ws, const float* __restrict__ bs,
    const float* __restrict__ We,
    int N)
{
    int n = blockIdx.x;
    if (n >= N) return;
    int j = threadIdx.x;  // 0..127
    int w = j >> 5;       // head
    int lane = j & 31;

    if (layer == 0 && j == 0) g_deg[n] = 0;   // prep for CSR histogram

    __shared__ float xs[32];
    if (j < 32) {
        float t = layer ? fmaxf(g_h1[n * 32 + j], 0.0f) : xin[n * 32 + j];
        xs[j] = t;
    }
    __syncthreads();

    float aq = bq[j], ak = bk[j], av = bv[j];
#pragma unroll
    for (int i = 0; i < 32; i++) {
        float xi = xs[i];
        aq = fmaf(xi, Wq[i * 128 + j], aq);
        ak = fmaf(xi, Wk[i * 128 + j], ak);
        av = fmaf(xi, Wv[i * 128 + j], av);
    }
    g_q[n * 128 + j] = aq;
    g_kv[(size_t)n * 128 + j] = __floats2half2_rn(ak, av);

#pragma unroll
    for (int i = 0; i < 16; i++) {
        float t = We[i * 128 + j] * aq;
#pragma unroll
        for (int off = 16; off > 0; off >>= 1)
            t += __shfl_xor_sync(0xffffffffu, t, off);
        if (lane == 0) g_G[n * 64 + w * 16 + i] = t;
    }

    if (j < 32) {
        float as = bs[j];
#pragma unroll
        for (int i = 0; i < 32; i++) as = fmaf(xs[i], Ws[i * 32 + j], as);
        float* outbuf = layer ? g_h2 : g_h1;
        outbuf[n * 32 + j] = as;
    }
}

// ===========================================================================
// Fused per-node attention: one warp per node, CSR loop, register
// accumulation, NO atomics. ea is STREAMING (easorted); kv is one 512B
// fp16 record carrying both k and v (4 LDG.32/edge).
// ===========================================================================
__global__ void node_attn_kernel(const float* __restrict__ We,
                                 int layer, int N)
{
    __shared__ float sWe[2048];  // 16 x 128
    for (int t = threadIdx.x; t < 2048; t += blockDim.x) sWe[t] = We[t];
    __syncthreads();

    int n = (int)((blockIdx.x * blockDim.x + threadIdx.x) >> 5);
    int lane = threadIdx.x & 31;
    if (n >= N) return;

    int rs = g_rowptr[n];
    int re = g_rowptr[n + 1];

    const float* qrow = &g_q[n * 128];
    float q0 = qrow[lane], q1 = qrow[32 + lane], q2 = qrow[64 + lane], q3 = qrow[96 + lane];
    float G0 = 0, G1 = 0, G2 = 0, G3 = 0;
    if (lane < 16) {
        const float* Grow = &g_G[n * 64];
        G0 = Grow[lane]; G1 = Grow[16 + lane]; G2 = Grow[32 + lane]; G3 = Grow[48 + lane];
    }

    float accO0 = 0, accO1 = 0, accO2 = 0, accO3 = 0;
    float accT0 = 0, accT1 = 0;            // T[hb,i], T[2+hb,i]
    float s0 = 0, s1 = 0, s2 = 0, s3 = 0;  // redundant across lanes
    int hb = lane >> 4;

#pragma unroll 2
    for (int p = rs; p < re; p++) {
        int src = g_srcsorted[p];
        float eav = (lane < 16) ? g_easorted[(size_t)p * 16 + lane] : 0.0f;

        const __half2* kv = &g_kv[(size_t)src * 128];
        float2 f0 = __half22float2(kv[lane]);
        float2 f1 = __half22float2(kv[32 + lane]);
        float2 f2 = __half22float2(kv[64 + lane]);
        float2 f3 = __half22float2(kv[96 + lane]);

        float a0 = fmaf(eav, G0, q0 * f0.x);
        float a1 = fmaf(eav, G1, q1 * f1.x);
        float a2 = fmaf(eav, G2, q2 * f2.x);
        float a3 = fmaf(eav, G3, q3 * f3.x);
#pragma unroll
        for (int off = 16; off >= 4; off >>= 1) {
            a0 += __shfl_xor_sync(0xffffffffu, a0, off);
            a1 += __shfl_xor_sync(0xffffffffu, a1, off);
            a2 += __shfl_xor_sync(0xffffffffu, a2, off);
            a3 += __shfl_xor_sync(0xffffffffu, a3, off);
        }
        // octet o takes head o; finish bits 0,1
        int o = lane >> 3;
        float r = a0;
        if (o == 1) r = a1;
        else if (o == 2) r = a2;
        else if (o == 3) r = a3;
        r += __shfl_xor_sync(0xffffffffu, r, 1);
        r += __shfl_xor_sync(0xffffffffu, r, 2);

        float av = __expf(r * 0.17677669529663687f);  // 1/sqrt(32)
        float e0 = __shfl_sync(0xffffffffu, av, 0);
        float e1 = __shfl_sync(0xffffffffu, av, 8);
        float e2 = __shfl_sync(0xffffffffu, av, 16);
        float e3 = __shfl_sync(0xffffffffu, av, 24);

        accO0 = fmaf(e0, f0.y, accO0);
        accO1 = fmaf(e1, f1.y, accO1);
        accO2 = fmaf(e2, f2.y, accO2);
        accO3 = fmaf(e3, f3.y, accO3);

        float eai = __shfl_sync(0xffffffffu, eav, lane & 15);
        accT0 = fmaf(hb ? e1 : e0, eai, accT0);
        accT1 = fmaf(hb ? e3 : e2, eai, accT1);

        s0 += e0; s1 += e1; s2 += e2; s3 += e3;
    }

    float inv0 = 1.0f / (s0 + 1e-16f);
    float inv1 = 1.0f / (s1 + 1e-16f);
    float inv2 = 1.0f / (s2 + 1e-16f);
    float inv3 = 1.0f / (s3 + 1e-16f);

    // v-part
    float res = inv0 * accO0;
    res = fmaf(inv1, accO1, res);
    res = fmaf(inv2, accO2, res);
    res = fmaf(inv3, accO3, res);

    // e-part: sum_h inv_h * sum_i We[i, h*32+lane] * T[h,i]
#pragma unroll
    for (int h = 0; h < 4; h++) {
        float acc = 0.0f;
#pragma unroll
        for (int i = 0; i < 16; i++) {
            float t = (h < 2) ? __shfl_sync(0xffffffffu, accT0, h * 16 + i)
                              : __shfl_sync(0xffffffffu, accT1, (h - 2) * 16 + i);
            acc = fmaf(sWe[i * 128 + h * 32 + lane], t, acc);
        }
        float inv = (h == 0) ? inv0 : (h == 1) ? inv1 : (h == 2) ? inv2 : inv3;
        res = fmaf(inv, acc, res);
    }

    float* outbuf = layer ? g_h2 : g_h1;
    outbuf[n * 32 + lane] += 0.25f * res;   // skip already there; no atomics
}

// ===========================================================================
// MLP node precompute: u_src = relu(h2)@Wm1[0:32], u_dst = relu(h2)@Wm1[48:80]
// ===========================================================================
__global__ void mlp_pre_kernel(const float* __restrict__ Wm1, int N)
{
    __shared__ float sWa[1024];
    __shared__ float sWc[1024];
    for (int t = threadIdx.x; t < 1024; t += blockDim.x) {
        sWa[t] = Wm1[t];
        sWc[t] = Wm1[1536 + t];
    }
    __syncthreads();

    int n = (int)((blockIdx.x * blockDim.x + threadIdx.x) >> 5);
    int lane = threadIdx.x & 31;
    if (n >= N) return;

    float r = fmaxf(g_h2[n * 32 + lane], 0.0f);
    float us = 0.0f, ud = 0.0f;
#pragma unroll
    for (int i = 0; i < 32; i++) {
        float xi = __shfl_sync(0xffffffffu, r, i);
        us = fmaf(xi, sWa[i * 32 + lane], us);
        ud = fmaf(xi, sWc[i * 32 + lane], ud);
    }
    g_us[n * 32 + lane] = us;
    g_ud[n * 32 + lane] = ud;
}

// ===========================================================================
// Edge MLP: one warp per edge (original order).
// ===========================================================================
__global__ void edge_mlp_kernel(
    const int* __restrict__ ei, const float* __restrict__ ea,
    const float* __restrict__ Wm1, const float* __restrict__ bm1,
    const float* __restrict__ Wm2, const float* __restrict__ bm2,
    float* __restrict__ out, int E)
{
    __shared__ float sWe2[512];
    __shared__ float sb1[32];
    __shared__ float sW2[32];
    for (int t = threadIdx.x; t < 512; t += blockDim.x) sWe2[t] = Wm1[1024 + t];
    if (threadIdx.x < 32) {
        sb1[threadIdx.x] = bm1[threadIdx.x];
        sW2[threadIdx.x] = Wm2[threadIdx.x];
    }
    __syncthreads();

    int e = (int)((blockIdx.x * blockDim.x + threadIdx.x) >> 5);
    int lane = threadIdx.x & 31;
    if (e >= E) return;

    int src = ei[e];
    int dst = ei[E + e];

    float eav = (lane < 16) ? ea[(size_t)e * 16 + lane] : 0.0f;

    float t = g_us[src * 32 + lane] + g_ud[dst * 32 + lane] + sb1[lane];
#pragma unroll
    for (int i = 0; i < 16; i++) {
        float xi = __shfl_sync(0xffffffffu, eav, i);
        t = fmaf(xi, sWe2[i * 32 + lane], t);
    }
    float o = fmaxf(t, 0.0f) * sW2[lane];
#pragma unroll
    for (int off = 16; off > 0; off >>= 1)
        o += __shfl_xor_sync(0xffffffffu, o, off);
    if (lane == 0) out[e] = o + bm2[0];
}

// ===========================================================================
extern "C" void kernel_launch(void* const* d_in, const int* in_sizes, int n_in,
                              void* d_out, int out_size)
{
    const float* x  = (const float*)d_in[0];
    const float* ea = (const float*)d_in[1];
    const int*   ei = (const int*)d_in[2];

    const float* Wq1 = (const float*)d_in[3];
    const float* bq1 = (const float*)d_in[4];
    const float* Wk1 = (const float*)d_in[5];
    const float* bk1 = (const float*)d_in[6];
    const float* Wv1 = (const float*)d_in[7];
    const float* bv1 = (const float*)d_in[8];
    const float* We1 = (const float*)d_in[9];
    const float* Ws1 = (const float*)d_in[10];
    const float* bs1 = (const float*)d_in[11];

    const float* Wq2 = (const float*)d_in[12];
    const float* bq2 = (const float*)d_in[13];
    const float* Wk2 = (const float*)d_in[14];
    const float* bk2 = (const float*)d_in[15];
    const float* Wv2 = (const float*)d_in[16];
    const float* bv2 = (const float*)d_in[17];
    const float* We2 = (const float*)d_in[18];
    const float* Ws2 = (const float*)d_in[19];
    const float* bs2 = (const float*)d_in[20];

    const float* Wm1 = (const float*)d_in[21];
    const float* bm1 = (const float*)d_in[22];
    const float* Wm2 = (const float*)d_in[23];
    const float* bm2 = (const float*)d_in[24];

    float* out = (float*)d_out;

    int N = in_sizes[0] / 32;
    int E = in_sizes[1] / 16;

    int eBlocks256     = (E + 255) / 256;
    int edgeWarpBlocks = (E + 7) / 8;
    int nodeWarpBlocks = (N + 7) / 8;
    int eaSortBlocks   = (E * 16 + 255) / 256;

    // 1: node_linear L1 (also zeroes g_deg)
    node_linear_kernel<<<N, 128>>>(x, 0, Wq1, bq1, Wk1, bk1, Wv1, bv1, Ws1, bs1, We1, N);
    // 2-5: CSR build + ea permute
    csr_hist_kernel<<<eBlocks256, 256>>>(ei, E);
    csr_scan_kernel<<<1, 1024>>>(N);
    csr_scatter_kernel<<<eBlocks256, 256>>>(ei, E);
    ea_sort_kernel<<<eaSortBlocks, 256>>>(ea, E);
    // 6: attention layer 1
    node_attn_kernel<<<nodeWarpBlocks, 256>>>(We1, 0, N);

    // ---- Layer 2 ----
    node_linear_kernel<<<N, 128>>>(nullptr, 1, Wq2, bq2, Wk2, bk2, Wv2, bv2, Ws2, bs2, We2, N);
    node_attn_kernel<<<nodeWarpBlocks, 256>>>(We2, 1, N);

    // ---- Edge MLP ----
    mlp_pre_kernel<<<nodeWarpBlocks, 256>>>(Wm1, N);
    edge_mlp_kernel<<<edgeWarpBlocks, 256>>>(ei, ea, Wm1, bm1, Wm2, bm2, out, E);
}

// round 16
// speedup vs baseline: 1.0386x; 1.0386x over previous
#include <cuda_runtime.h>

// Problem dims (fixed by the dataset; runtime values derived from in_sizes).
#define NMAX 50000
#define EMAX 800000

// ---- scratch (device globals; no allocation allowed) ----
__device__ float g_q[NMAX * 128];
__device__ float g_kv[NMAX * 256];  // k row [0:128), v row [128:256) per node
__device__ float g_G[NMAX * 64];    // G[n,h*16+i] = sum_d We[i,h*32+d] * q[n,h*32+d]
__device__ float g_h1[NMAX * 32];   // layer-1 output (skip + attention)
__device__ float g_h2[NMAX * 32];   // layer-2 output
__device__ float g_us[NMAX * 32];   // relu(h2) @ Wm1[0:32]
__device__ float g_ud[NMAX * 32];   // relu(h2) @ Wm1[48:80]
__device__ float g_easorted[EMAX * 16];  // ea rows permuted into dst-sorted order

// ---- CSR (dst-sorted edges), built once per launch ----
// INVARIANT: g_deg is all-zero at the START of every kernel_launch sequence
// (device globals are zero-initialized; csr_scatter re-zeroes it each run).
__device__ int g_deg[NMAX];
__device__ int g_rowptr[NMAX + 1];
__device__ int g_cursor[NMAX];
__device__ int g_srcsorted[EMAX];

// ===========================================================================
// Single-block exclusive scan over g_deg -> g_rowptr / g_cursor.
// ===========================================================================
__global__ void csr_scan_kernel(int N) {
    __shared__ int warpsums[32];
    __shared__ int s_carry;
    int tid = threadIdx.x;
    int lane = tid & 31;
    int w = tid >> 5;
    if (tid == 0) s_carry = 0;
    __syncthreads();

    for (int base = 0; base < N; base += 1024) {
        int i = base + tid;
        int v = (i < N) ? g_deg[i] : 0;
        int x = v;
#pragma unroll
        for (int off = 1; off < 32; off <<= 1) {
            int t = __shfl_up_sync(0xffffffffu, x, off);
            if (lane >= off) x += t;
        }
        if (lane == 31) warpsums[w] = x;
        __syncthreads();
        if (w == 0) {
            int y = warpsums[lane];
#pragma unroll
            for (int off = 1; off < 32; off <<= 1) {
                int t = __shfl_up_sync(0xffffffffu, y, off);
                if (lane >= off) y += t;
            }
            warpsums[lane] = y;
        }
        __syncthreads();
        int incl = x + (w ? warpsums[w - 1] : 0) + s_carry;
        if (i < N) {
            g_rowptr[i + 1] = incl;
            g_cursor[i] = incl - v;
        }
        __syncthreads();               // everyone has read s_carry
        if (tid == 1023) s_carry = incl;
        __syncthreads();
    }
    if (tid == 0) g_rowptr[0] = 0;
}

// ===========================================================================
// Scatter edges into dst-sorted order; ALSO permutes ea rows and re-zeroes
// g_deg for the next replay (tail-zero invariant).
// ===========================================================================
__global__ void csr_scatter_kernel(const int* __restrict__ ei,
                                   const float* __restrict__ ea,
                                   int E, int N) {
    int e = blockIdx.x * blockDim.x + threadIdx.x;
    if (e < N) g_deg[e] = 0;           // prep for NEXT run's histogram
    if (e >= E) return;
    int src = ei[e];
    int dst = ei[E + e];
    int p = atomicAdd(&g_cursor[dst], 1);
    g_srcsorted[p] = src;
    const float4* s = reinterpret_cast<const float4*>(&ea[(size_t)e * 16]);
    float4* d = reinterpret_cast<float4*>(&g_easorted[(size_t)p * 16]);
    float4 s0 = s[0], s1 = s[1], s2 = s[2], s3 = s[3];
    d[0] = s0; d[1] = s1; d[2] = s2; d[3] = s3;
}

// ===========================================================================
// Node linears: q = x@Wq+b ([N,128]); k,v into g_kv; skip = x@Ws+bs into
// outbuf; G[n, w*16+i] = sum_d We[i, w*32+d] * q[n, w*32+d].
// One block per node, 128 threads.
// Layer 0 ALSO does the CSR dst-histogram for its slice of 16 edges
// (g_deg is zero at sequence start by invariant).
// ===========================================================================
__global__ void node_linear_kernel(
    const float* __restrict__ xin, int layer,
    const float* __restrict__ Wq, const float* __restrict__ bq,
    const float* __restrict__ Wk, const float* __restrict__ bk,
    const float* __restrict__ Wv, const float* __restrict__ bv,
    const float* __restrict__ Ws, const float* __restrict__ bs,
    const float* __restrict__ We,
    const int* __restrict__ ei, int E,
    int N)
{
    int n = blockIdx.x;
    if (n >= N) return;
    int j = threadIdx.x;  // 0..127
    int w = j >> 5;       // head
    int lane = j & 31;

    if (layer == 0) {
        int epb = (E + N - 1) / N;     // 16 for this dataset
        if (j < epb) {
            int e = n * epb + j;
            if (e < E) atomicAdd(&g_deg[ei[E + e]], 1);
        }
    }

    __shared__ float xs[32];
    if (j < 32) {
        float t = layer ? fmaxf(g_h1[n * 32 + j], 0.0f) : xin[n * 32 + j];
        xs[j] = t;
    }
    __syncthreads();

    float aq = bq[j], ak = bk[j], av = bv[j];
#pragma unroll
    for (int i = 0; i < 32; i++) {
        float xi = xs[i];
        aq = fmaf(xi, Wq[i * 128 + j], aq);
        ak = fmaf(xi, Wk[i * 128 + j], ak);
        av = fmaf(xi, Wv[i * 128 + j], av);
    }
    g_q[n * 128 + j] = aq;
    g_kv[(size_t)n * 256 + j] = ak;
    g_kv[(size_t)n * 256 + 128 + j] = av;

#pragma unroll
    for (int i = 0; i < 16; i++) {
        float t = We[i * 128 + j] * aq;
#pragma unroll
        for (int off = 16; off > 0; off >>= 1)
            t += __shfl_xor_sync(0xffffffffu, t, off);
        if (lane == 0) g_G[n * 64 + w * 16 + i] = t;
    }

    if (j < 32) {
        float as = bs[j];
#pragma unroll
        for (int i = 0; i < 32; i++) as = fmaf(xs[i], Ws[i * 32 + j], as);
        float* outbuf = layer ? g_h2 : g_h1;
        outbuf[n * 32 + j] = as;
    }
}

// ===========================================================================
// Fused per-node attention: one warp per node, CSR loop, register
// accumulation, NO atomics. Manual 2-edge pipeline: all loads for two edges
// are issued before either reduction chain (2x loads-in-flight per warp).
// ===========================================================================
__global__ void node_attn_kernel(const float* __restrict__ We,
                                 int layer, int N)
{
    __shared__ float sWe[2048];  // 16 x 128
    for (int t = threadIdx.x; t < 2048; t += blockDim.x) sWe[t] = We[t];
    __syncthreads();

    int n = (int)((blockIdx.x * blockDim.x + threadIdx.x) >> 5);
    int lane = threadIdx.x & 31;
    if (n >= N) return;

    int rs = g_rowptr[n];
    int re = g_rowptr[n + 1];

    const float* qrow = &g_q[n * 128];
    float q0 = qrow[lane], q1 = qrow[32 + lane], q2 = qrow[64 + lane], q3 = qrow[96 + lane];
    float G0 = 0, G1 = 0, G2 = 0, G3 = 0;
    if (lane < 16) {
        const float* Grow = &g_G[n * 64];
        G0 = Grow[lane]; G1 = Grow[16 + lane]; G2 = Grow[32 + lane]; G3 = Grow[48 + lane];
    }

    float accO0 = 0, accO1 = 0, accO2 = 0, accO3 = 0;
    float accT0 = 0, accT1 = 0;            // T[hb,i], T[2+hb,i]
    float s0 = 0, s1 = 0, s2 = 0, s3 = 0;  // redundant across lanes
    int hb = lane >> 4;

    for (int p = rs; p < re; p += 2) {
        bool hasB = (p + 1) < re;
        int pa = p;
        int pb = hasB ? p + 1 : p;

        // ---- issue ALL loads for both edges up front ----
        int srcA = g_srcsorted[pa];
        int srcB = g_srcsorted[pb];
        float eavA = (lane < 16) ? g_easorted[(size_t)pa * 16 + lane] : 0.0f;
        float eavB = (lane < 16) ? g_easorted[(size_t)pb * 16 + lane] : 0.0f;

        const float* kvA = &g_kv[(size_t)srcA * 256];
        const float* kvB = &g_kv[(size_t)srcB * 256];
        float kA0 = kvA[lane], kA1 = kvA[32 + lane], kA2 = kvA[64 + lane], kA3 = kvA[96 + lane];
        float vA0 = kvA[128 + lane], vA1 = kvA[160 + lane], vA2 = kvA[192 + lane], vA3 = kvA[224 + lane];
        float kB0 = kvB[lane], kB1 = kvB[32 + lane], kB2 = kvB[64 + lane], kB3 = kvB[96 + lane];
        float vB0 = kvB[128 + lane], vB1 = kvB[160 + lane], vB2 = kvB[192 + lane], vB3 = kvB[224 + lane];

        // ---- two independent alpha chains, interleaved ----
        float a0 = fmaf(eavA, G0, q0 * kA0);
        float b0 = fmaf(eavB, G0, q0 * kB0);
        float a1 = fmaf(eavA, G1, q1 * kA1);
        float b1 = fmaf(eavB, G1, q1 * kB1);
        float a2 = fmaf(eavA, G2, q2 * kA2);
        float b2 = fmaf(eavB, G2, q2 * kB2);
        float a3 = fmaf(eavA, G3, q3 * kA3);
        float b3 = fmaf(eavB, G3, q3 * kB3);

#pragma unroll
        for (int off = 16; off >= 4; off >>= 1) {
            a0 += __shfl_xor_sync(0xffffffffu, a0, off);
            b0 += __shfl_xor_sync(0xffffffffu, b0, off);
            a1 += __shfl_xor_sync(0xffffffffu, a1, off);
            b1 += __shfl_xor_sync(0xffffffffu, b1, off);
            a2 += __shfl_xor_sync(0xffffffffu, a2, off);
            b2 += __shfl_xor_sync(0xffffffffu, b2, off);
            a3 += __shfl_xor_sync(0xffffffffu, a3, off);
            b3 += __shfl_xor_sync(0xffffffffu, b3, off);
        }
        // octet o takes head o; finish bits 0,1
        int o = lane >> 3;
        float rA = a0, rB = b0;
        if (o == 1) { rA = a1; rB = b1; }
        else if (o == 2) { rA = a2; rB = b2; }
        else if (o == 3) { rA = a3; rB = b3; }
        rA += __shfl_xor_sync(0xffffffffu, rA, 1);
        rB += __shfl_xor_sync(0xffffffffu, rB, 1);
        rA += __shfl_xor_sync(0xffffffffu, rA, 2);
        rB += __shfl_xor_sync(0xffffffffu, rB, 2);

        float avA = __expf(rA * 0.17677669529663687f);  // 1/sqrt(32)
        float avB = __expf(rB * 0.17677669529663687f);
        if (!hasB) avB = 0.0f;   // dummy edge contributes nothing

        float eA0 = __shfl_sync(0xffffffffu, avA, 0);
        float eB0 = __shfl_sync(0xffffffffu, avB, 0);
        float eA1 = __shfl_sync(0xffffffffu, avA, 8);
        float eB1 = __shfl_sync(0xffffffffu, avB, 8);
        float eA2 = __shfl_sync(0xffffffffu, avA, 16);
        float eB2 = __shfl_sync(0xffffffffu, avB, 16);
        float eA3 = __shfl_sync(0xffffffffu, avA, 24);
        float eB3 = __shfl_sync(0xffffffffu, avB, 24);

        accO0 = fmaf(eA0, vA0, accO0); accO0 = fmaf(eB0, vB0, accO0);
        accO1 = fmaf(eA1, vA1, accO1); accO1 = fmaf(eB1, vB1, accO1);
        accO2 = fmaf(eA2, vA2, accO2); accO2 = fmaf(eB2, vB2, accO2);
        accO3 = fmaf(eA3, vA3, accO3); accO3 = fmaf(eB3, vB3, accO3);

        float eaiA = __shfl_sync(0xffffffffu, eavA, lane & 15);
        float eaiB = __shfl_sync(0xffffffffu, eavB, lane & 15);
        accT0 = fmaf(hb ? eA1 : eA0, eaiA, accT0);
        accT0 = fmaf(hb ? eB1 : eB0, eaiB, accT0);
        accT1 = fmaf(hb ? eA3 : eA2, eaiA, accT1);
        accT1 = fmaf(hb ? eB3 : eB2, eaiB, accT1);

        s0 += eA0 + eB0;
        s1 += eA1 + eB1;
        s2 += eA2 + eB2;
        s3 += eA3 + eB3;
    }

    float inv0 = 1.0f / (s0 + 1e-16f);
    float inv1 = 1.0f / (s1 + 1e-16f);
    float inv2 = 1.0f / (s2 + 1e-16f);
    float inv3 = 1.0f / (s3 + 1e-16f);

    // v-part
    float res = inv0 * accO0;
    res = fmaf(inv1, accO1, res);
    res = fmaf(inv2, accO2, res);
    res = fmaf(inv3, accO3, res);

    // e-part: sum_h inv_h * sum_i We[i, h*32+lane] * T[h,i]
#pragma unroll
    for (int h = 0; h < 4; h++) {
        float acc = 0.0f;
#pragma unroll
        for (int i = 0; i < 16; i++) {
            float t = (h < 2) ? __shfl_sync(0xffffffffu, accT0, h * 16 + i)
                              : __shfl_sync(0xffffffffu, accT1, (h - 2) * 16 + i);
            acc = fmaf(sWe[i * 128 + h * 32 + lane], t, acc);
        }
        float inv = (h == 0) ? inv0 : (h == 1) ? inv1 : (h == 2) ? inv2 : inv3;
        res = fmaf(inv, acc, res);
    }

    float* outbuf = layer ? g_h2 : g_h1;
    outbuf[n * 32 + lane] += 0.25f * res;   // skip already there; no atomics
}

// ===========================================================================
// MLP node precompute: u_src = relu(h2)@Wm1[0:32], u_dst = relu(h2)@Wm1[48:80]
// ===========================================================================
__global__ void mlp_pre_kernel(const float* __restrict__ Wm1, int N)
{
    __shared__ float sWa[1024];
    __shared__ float sWc[1024];
    for (int t = threadIdx.x; t < 1024; t += blockDim.x) {
        sWa[t] = Wm1[t];
        sWc[t] = Wm1[1536 + t];
    }
    __syncthreads();

    int n = (int)((blockIdx.x * blockDim.x + threadIdx.x) >> 5);
    int lane = threadIdx.x & 31;
    if (n >= N) return;

    float r = fmaxf(g_h2[n * 32 + lane], 0.0f);
    float us = 0.0f, ud = 0.0f;
#pragma unroll
    for (int i = 0; i < 32; i++) {
        float xi = __shfl_sync(0xffffffffu, r, i);
        us = fmaf(xi, sWa[i * 32 + lane], us);
        ud = fmaf(xi, sWc[i * 32 + lane], ud);
    }
    g_us[n * 32 + lane] = us;
    g_ud[n * 32 + lane] = ud;
}

// ===========================================================================
// Edge MLP: one warp per edge (original order).
// ===========================================================================
__global__ void edge_mlp_kernel(
    const int* __restrict__ ei, const float* __restrict__ ea,
    const float* __restrict__ Wm1, const float* __restrict__ bm1,
    const float* __restrict__ Wm2, const float* __restrict__ bm2,
    float* __restrict__ out, int E)
{
    __shared__ float sWe2[512];
    __shared__ float sb1[32];
    __shared__ float sW2[32];
    for (int t = threadIdx.x; t < 512; t += blockDim.x) sWe2[t] = Wm1[1024 + t];
    if (threadIdx.x < 32) {
        sb1[threadIdx.x] = bm1[threadIdx.x];
        sW2[threadIdx.x] = Wm2[threadIdx.x];
    }
    __syncthreads();

    int e = (int)((blockIdx.x * blockDim.x + threadIdx.x) >> 5);
    int lane = threadIdx.x & 31;
    if (e >= E) return;

    int src = ei[e];
    int dst = ei[E + e];

    float eav = (lane < 16) ? ea[(size_t)e * 16 + lane] : 0.0f;

    float t = g_us[src * 32 + lane] + g_ud[dst * 32 + lane] + sb1[lane];
#pragma unroll
    for (int i = 0; i < 16; i++) {
        float xi = __shfl_sync(0xffffffffu, eav, i);
        t = fmaf(xi, sWe2[i * 32 + lane], t);
    }
    float o = fmaxf(t, 0.0f) * sW2[lane];
#pragma unroll
    for (int off = 16; off > 0; off >>= 1)
        o += __shfl_xor_sync(0xffffffffu, o, off);
    if (lane == 0) out[e] = o + bm2[0];
}

// ===========================================================================
extern "C" void kernel_launch(void* const* d_in, const int* in_sizes, int n_in,
                              void* d_out, int out_size)
{
    const float* x  = (const float*)d_in[0];
    const float* ea = (const float*)d_in[1];
    const int*   ei = (const int*)d_in[2];

    const float* Wq1 = (const float*)d_in[3];
    const float* bq1 = (const float*)d_in[4];
    const float* Wk1 = (const float*)d_in[5];
    const float* bk1 = (const float*)d_in[6];
    const float* Wv1 = (const float*)d_in[7];
    const float* bv1 = (const float*)d_in[8];
    const float* We1 = (const float*)d_in[9];
    const float* Ws1 = (const float*)d_in[10];
    const float* bs1 = (const float*)d_in[11];

    const float* Wq2 = (const float*)d_in[12];
    const float* bq2 = (const float*)d_in[13];
    const float* Wk2 = (const float*)d_in[14];
    const float* bk2 = (const float*)d_in[15];
    const float* Wv2 = (const float*)d_in[16];
    const float* bv2 = (const float*)d_in[17];
    const float* We2 = (const float*)d_in[18];
    const float* Ws2 = (const float*)d_in[19];
    const float* bs2 = (const float*)d_in[20];

    const float* Wm1 = (const float*)d_in[21];
    const float* bm1 = (const float*)d_in[22];
    const float* Wm2 = (const float*)d_in[23];
    const float* bm2 = (const float*)d_in[24];

    float* out = (float*)d_out;

    int N = in_sizes[0] / 32;
    int E = in_sizes[1] / 16;

    int edgeWarpBlocks = (E + 7) / 8;
    int nodeWarpBlocks = (N + 7) / 8;
    int scatBlocks     = ((E > N ? E : N) + 255) / 256;

    // Launch order arranged so the profiled slot (my 4th launch) is
    // node_attn layer 1.
    // 1: node_linear L1 (+dst histogram; g_deg==0 by tail-zero invariant)
    node_linear_kernel<<<N, 128>>>(x, 0, Wq1, bq1, Wk1, bk1, Wv1, bv1, Ws1, bs1, We1, ei, E, N);
    // 2: prefix scan -> rowptr/cursor
    csr_scan_kernel<<<1, 1024>>>(N);
    // 3: scatter (+ea permute, +deg re-zero for next replay)
    csr_scatter_kernel<<<scatBlocks, 256>>>(ei, ea, E, N);
    // 4: attention layer 1   <-- profiled launch
    node_attn_kernel<<<nodeWarpBlocks, 256>>>(We1, 0, N);

    // ---- Layer 2 ----
    node_linear_kernel<<<N, 128>>>(nullptr, 1, Wq2, bq2, Wk2, bk2, Wv2, bv2, Ws2, bs2, We2, ei, E, N);
    node_attn_kernel<<<nodeWarpBlocks, 256>>>(We2, 1, N);

    // ---- Edge MLP ----
    mlp_pre_kernel<<<nodeWarpBlocks, 256>>>(Wm1, N);
    edge_mlp_kernel<<<edgeWarpBlocks, 256>>>(ei, ea, Wm1, bm1, Wm2, bm2, out, E);
}

// round 17
// speedup vs baseline: 1.3899x; 1.3383x over previous
#include <cuda_runtime.h>

// Problem dims (fixed by the dataset; runtime values derived from in_sizes).
#define NMAX 50000
#define EMAX 800000

// ---- scratch (device globals; no allocation allowed) ----
__device__ float g_q[NMAX * 128];
__device__ float g_kv[NMAX * 256];  // k row [0:128), v row [128:256) per node
__device__ float g_G[NMAX * 64];    // G[n,h*16+i] = sum_d We[i,h*32+d] * q[n,h*32+d]
__device__ float g_h1[NMAX * 32];   // layer-1 output (skip + attention)
__device__ float g_h2[NMAX * 32];   // layer-2 output
__device__ float g_us[NMAX * 32];   // relu(h2) @ Wm1[0:32]
__device__ float g_ud[NMAX * 32];   // relu(h2) @ Wm1[48:80]
__device__ float g_easorted[EMAX * 16];  // ea rows permuted into dst-sorted order

// ---- CSR (dst-sorted edges), built once per launch ----
// INVARIANT: g_deg is all-zero at the START of every kernel_launch sequence
// (device globals are zero-initialized; csr_scatter re-zeroes it each run).
__device__ int g_deg[NMAX];
__device__ int g_rowptr[NMAX + 1];
__device__ int g_cursor[NMAX];
__device__ int g_srcsorted[EMAX];

// ===========================================================================
// Single-block exclusive scan over g_deg -> g_rowptr / g_cursor.
// ===========================================================================
__global__ void csr_scan_kernel(int N) {
    __shared__ int warpsums[32];
    __shared__ int s_carry;
    int tid = threadIdx.x;
    int lane = tid & 31;
    int w = tid >> 5;
    if (tid == 0) s_carry = 0;
    __syncthreads();

    for (int base = 0; base < N; base += 1024) {
        int i = base + tid;
        int v = (i < N) ? g_deg[i] : 0;
        int x = v;
#pragma unroll
        for (int off = 1; off < 32; off <<= 1) {
            int t = __shfl_up_sync(0xffffffffu, x, off);
            if (lane >= off) x += t;
        }
        if (lane == 31) warpsums[w] = x;
        __syncthreads();
        if (w == 0) {
            int y = warpsums[lane];
#pragma unroll
            for (int off = 1; off < 32; off <<= 1) {
                int t = __shfl_up_sync(0xffffffffu, y, off);
                if (lane >= off) y += t;
            }
            warpsums[lane] = y;
        }
        __syncthreads();
        int incl = x + (w ? warpsums[w - 1] : 0) + s_carry;
        if (i < N) {
            g_rowptr[i + 1] = incl;
            g_cursor[i] = incl - v;
        }
        __syncthreads();               // everyone has read s_carry
        if (tid == 1023) s_carry = incl;
        __syncthreads();
    }
    if (tid == 0) g_rowptr[0] = 0;
}

// ===========================================================================
// Scatter edges into dst-sorted order; ALSO permutes ea rows and re-zeroes
// g_deg for the next replay (tail-zero invariant).
// ===========================================================================
__global__ void csr_scatter_kernel(const int* __restrict__ ei,
                                   const float* __restrict__ ea,
                                   int E, int N) {
    int e = blockIdx.x * blockDim.x + threadIdx.x;
    if (e < N) g_deg[e] = 0;           // prep for NEXT run's histogram
    if (e >= E) return;
    int src = ei[e];
    int dst = ei[E + e];
    int p = atomicAdd(&g_cursor[dst], 1);
    g_srcsorted[p] = src;
    const float4* s = reinterpret_cast<const float4*>(&ea[(size_t)e * 16]);
    float4* d = reinterpret_cast<float4*>(&g_easorted[(size_t)p * 16]);
    float4 s0 = s[0], s1 = s[1], s2 = s[2], s3 = s[3];
    d[0] = s0; d[1] = s1; d[2] = s2; d[3] = s3;
}

// ===========================================================================
// Node linears (vectorized): block=128 threads, one node.
//   warp 0: q (float4 cols 4l..4l+3) + G via octet reduce
//   warp 1: k, warp 2: v  -> g_kv plain layout
//   warp 3: skip (8 lanes x float4) + dst-histogram (layer 0)
// ===========================================================================
__global__ void node_linear_kernel(
    const float* __restrict__ xin, int layer,
    const float* __restrict__ Wq, const float* __restrict__ bq,
    const float* __restrict__ Wk, const float* __restrict__ bk,
    const float* __restrict__ Wv, const float* __restrict__ bv,
    const float* __restrict__ Ws, const float* __restrict__ bs,
    const float* __restrict__ We,
    const int* __restrict__ ei, int E,
    int N)
{
    int n = blockIdx.x;
    if (n >= N) return;
    int tid = threadIdx.x;
    int w = tid >> 5;
    int l = tid & 31;

    __shared__ float xs[32];
    if (tid < 32) {
        float t = layer ? fmaxf(g_h1[n * 32 + tid], 0.0f) : xin[n * 32 + tid];
        xs[tid] = t;
    }
    if (w == 3 && layer == 0) {
        int epb = (E + N - 1) / N;     // 16 for this dataset
        if (l < epb) {
            int e = n * epb + l;
            if (e < E) atomicAdd(&g_deg[ei[E + e]], 1);
        }
    }
    __syncthreads();

    if (w < 3) {
        const float* W = (w == 0) ? Wq : (w == 1) ? Wk : Wv;
        const float* b = (w == 0) ? bq : (w == 1) ? bk : bv;
        const float4* W4 = reinterpret_cast<const float4*>(W);
        float4 acc = reinterpret_cast<const float4*>(b)[l];
#pragma unroll
        for (int i = 0; i < 32; i++) {
            float4 w4 = W4[i * 32 + l];
            float xi = xs[i];
            acc.x = fmaf(xi, w4.x, acc.x);
            acc.y = fmaf(xi, w4.y, acc.y);
            acc.z = fmaf(xi, w4.z, acc.z);
            acc.w = fmaf(xi, w4.w, acc.w);
        }
        if (w == 0) {
            reinterpret_cast<float4*>(&g_q[(size_t)n * 128])[l] = acc;
            // G via octet reduce: lane l covers cols 4l..4l+3, head h = l>>3
            const float4* We4 = reinterpret_cast<const float4*>(We);
#pragma unroll
            for (int i = 0; i < 16; i++) {
                float4 we4 = We4[i * 32 + l];
                float t = acc.x * we4.x + acc.y * we4.y + acc.z * we4.z + acc.w * we4.w;
                t += __shfl_xor_sync(0xffffffffu, t, 1);
                t += __shfl_xor_sync(0xffffffffu, t, 2);
                t += __shfl_xor_sync(0xffffffffu, t, 4);
                if ((l & 7) == 0) g_G[n * 64 + (l >> 3) * 16 + i] = t;
            }
        } else if (w == 1) {
            reinterpret_cast<float4*>(&g_kv[(size_t)n * 256])[l] = acc;
        } else {
            reinterpret_cast<float4*>(&g_kv[(size_t)n * 256 + 128])[l] = acc;
        }
    } else {
        // skip: lanes 0..7 compute cols 4l..4l+3 of x@Ws+bs
        if (l < 8) {
            const float4* Ws4 = reinterpret_cast<const float4*>(Ws);
            float4 acc = reinterpret_cast<const float4*>(bs)[l];
#pragma unroll
            for (int i = 0; i < 32; i++) {
                float4 w4 = Ws4[i * 8 + l];
                float xi = xs[i];
                acc.x = fmaf(xi, w4.x, acc.x);
                acc.y = fmaf(xi, w4.y, acc.y);
                acc.z = fmaf(xi, w4.z, acc.z);
                acc.w = fmaf(xi, w4.w, acc.w);
            }
            float* outbuf = layer ? g_h2 : g_h1;
            reinterpret_cast<float4*>(&outbuf[(size_t)n * 32])[l] = acc;
        }
    }
}

// ===========================================================================
// Fused per-node attention, OCTET layout: lane l = 8h+m -> head h, chunk m.
// All operands are vector loads from the existing plain layouts:
//   q4/k4/v4 = float4 elem l  (cols h*32+4m..+3),  G2 = float2 elem l,
//   ea2 = float2 elem (l&7).
// Per edge: 4 LDG + 3 SHFL + ~13 FMA. exp redundant per octet. NO atomics.
// ===========================================================================
__global__ void node_attn_kernel(const float* __restrict__ We,
                                 int layer, int N)
{
    __shared__ float4 sWe4[512];  // We as float4 (16 x 32)
    {
        const float4* We4 = reinterpret_cast<const float4*>(We);
        for (int t = threadIdx.x; t < 512; t += blockDim.x) sWe4[t] = We4[t];
    }
    __syncthreads();

    int n = (int)((blockIdx.x * blockDim.x + threadIdx.x) >> 5);
    int lane = threadIdx.x & 31;
    if (n >= N) return;

    int rs = g_rowptr[n];
    int re = g_rowptr[n + 1];

    // per-node loads: q4 covers cols h*32+4m..+3 == float4 element `lane`
    float4 q4 = reinterpret_cast<const float4*>(&g_q[(size_t)n * 128])[lane];
    float2 G2 = reinterpret_cast<const float2*>(&g_G[(size_t)n * 64])[lane];

    float4 accO = make_float4(0.f, 0.f, 0.f, 0.f);
    float accT0 = 0.f, accT1 = 0.f;   // T[h,2m], T[h,2m+1]
    float s = 0.f;                     // s_h (redundant across octet)
    int m8 = lane & 7;

#pragma unroll 2
    for (int p = rs; p < re; p++) {
        int src = g_srcsorted[p];
        float2 ea2 = reinterpret_cast<const float2*>(&g_easorted[(size_t)p * 16])[m8];

        const float4* kvp = reinterpret_cast<const float4*>(&g_kv[(size_t)src * 256]);
        float4 k4 = kvp[lane];
        float4 v4 = kvp[32 + lane];

        float r = q4.x * k4.x;
        r = fmaf(q4.y, k4.y, r);
        r = fmaf(q4.z, k4.z, r);
        r = fmaf(q4.w, k4.w, r);
        r = fmaf(G2.x, ea2.x, r);
        r = fmaf(G2.y, ea2.y, r);
        // octet reduce -> every lane in octet has alpha_h
        r += __shfl_xor_sync(0xffffffffu, r, 1);
        r += __shfl_xor_sync(0xffffffffu, r, 2);
        r += __shfl_xor_sync(0xffffffffu, r, 4);

        float e = __expf(r * 0.17677669529663687f);  // 1/sqrt(32)

        s += e;
        accO.x = fmaf(e, v4.x, accO.x);
        accO.y = fmaf(e, v4.y, accO.y);
        accO.z = fmaf(e, v4.z, accO.z);
        accO.w = fmaf(e, v4.w, accO.w);
        accT0 = fmaf(e, ea2.x, accT0);
        accT1 = fmaf(e, ea2.y, accT1);
    }

    float inv = 1.0f / (s + 1e-16f);   // inv_h, redundant per octet

    // e-part: ep4.j = sum_i We[i, h*32+4m+j] * T[h,i]
    // T[h,i] lives at lane (l&24)+(i>>1), register accT(i&1)
    float4 ep = make_float4(0.f, 0.f, 0.f, 0.f);
    int obase = lane & 24;
#pragma unroll
    for (int i = 0; i < 16; i++) {
        float tb = (i & 1) ? accT1 : accT0;
        float t = __shfl_sync(0xffffffffu, tb, obase + (i >> 1));
        float4 we4 = sWe4[i * 32 + lane];
        ep.x = fmaf(t, we4.x, ep.x);
        ep.y = fmaf(t, we4.y, ep.y);
        ep.z = fmaf(t, we4.z, ep.z);
        ep.w = fmaf(t, we4.w, ep.w);
    }

    // total per head, then reduce across heads (lane bits 3,4)
    float4 tot;
    tot.x = inv * (accO.x + ep.x);
    tot.y = inv * (accO.y + ep.y);
    tot.z = inv * (accO.z + ep.z);
    tot.w = inv * (accO.w + ep.w);
#pragma unroll
    for (int off = 8; off <= 16; off <<= 1) {
        tot.x += __shfl_xor_sync(0xffffffffu, tot.x, off);
        tot.y += __shfl_xor_sync(0xffffffffu, tot.y, off);
        tot.z += __shfl_xor_sync(0xffffffffu, tot.z, off);
        tot.w += __shfl_xor_sync(0xffffffffu, tot.w, off);
    }

    // lanes 0..7 write cols 4m..4m+3 (skip already seeded; no atomics)
    if (lane < 8) {
        float* outbuf = layer ? g_h2 : g_h1;
        float4* o4 = reinterpret_cast<float4*>(&outbuf[(size_t)n * 32]);
        float4 cur = o4[lane];
        cur.x = fmaf(0.25f, tot.x, cur.x);
        cur.y = fmaf(0.25f, tot.y, cur.y);
        cur.z = fmaf(0.25f, tot.z, cur.z);
        cur.w = fmaf(0.25f, tot.w, cur.w);
        o4[lane] = cur;
    }
}

// ===========================================================================
// MLP node precompute: u_src = relu(h2)@Wm1[0:32], u_dst = relu(h2)@Wm1[48:80]
// ===========================================================================
__global__ void mlp_pre_kernel(const float* __restrict__ Wm1, int N)
{
    __shared__ float sWa[1024];
    __shared__ float sWc[1024];
    for (int t = threadIdx.x; t < 1024; t += blockDim.x) {
        sWa[t] = Wm1[t];
        sWc[t] = Wm1[1536 + t];
    }
    __syncthreads();

    int n = (int)((blockIdx.x * blockDim.x + threadIdx.x) >> 5);
    int lane = threadIdx.x & 31;
    if (n >= N) return;

    float r = fmaxf(g_h2[n * 32 + lane], 0.0f);
    float us = 0.0f, ud = 0.0f;
#pragma unroll
    for (int i = 0; i < 32; i++) {
        float xi = __shfl_sync(0xffffffffu, r, i);
        us = fmaf(xi, sWa[i * 32 + lane], us);
        ud = fmaf(xi, sWc[i * 32 + lane], ud);
    }
    g_us[n * 32 + lane] = us;
    g_ud[n * 32 + lane] = ud;
}

// ===========================================================================
// Edge MLP: one warp per edge (original order).
// ===========================================================================
__global__ void edge_mlp_kernel(
    const int* __restrict__ ei, const float* __restrict__ ea,
    const float* __restrict__ Wm1, const float* __restrict__ bm1,
    const float* __restrict__ Wm2, const float* __restrict__ bm2,
    float* __restrict__ out, int E)
{
    __shared__ float sWe2[512];
    __shared__ float sb1[32];
    __shared__ float sW2[32];
    for (int t = threadIdx.x; t < 512; t += blockDim.x) sWe2[t] = Wm1[1024 + t];
    if (threadIdx.x < 32) {
        sb1[threadIdx.x] = bm1[threadIdx.x];
        sW2[threadIdx.x] = Wm2[threadIdx.x];
    }
    __syncthreads();

    int e = (int)((blockIdx.x * blockDim.x + threadIdx.x) >> 5);
    int lane = threadIdx.x & 31;
    if (e >= E) return;

    int src = ei[e];
    int dst = ei[E + e];

    float eav = (lane < 16) ? ea[(size_t)e * 16 + lane] : 0.0f;

    float t = g_us[src * 32 + lane] + g_ud[dst * 32 + lane] + sb1[lane];
#pragma unroll
    for (int i = 0; i < 16; i++) {
        float xi = __shfl_sync(0xffffffffu, eav, i);
        t = fmaf(xi, sWe2[i * 32 + lane], t);
    }
    float o = fmaxf(t, 0.0f) * sW2[lane];
#pragma unroll
    for (int off = 16; off > 0; off >>= 1)
        o += __shfl_xor_sync(0xffffffffu, o, off);
    if (lane == 0) out[e] = o + bm2[0];
}

// ===========================================================================
extern "C" void kernel_launch(void* const* d_in, const int* in_sizes, int n_in,
                              void* d_out, int out_size)
{
    const float* x  = (const float*)d_in[0];
    const float* ea = (const float*)d_in[1];
    const int*   ei = (const int*)d_in[2];

    const float* Wq1 = (const float*)d_in[3];
    const float* bq1 = (const float*)d_in[4];
    const float* Wk1 = (const float*)d_in[5];
    const float* bk1 = (const float*)d_in[6];
    const float* Wv1 = (const float*)d_in[7];
    const float* bv1 = (const float*)d_in[8];
    const float* We1 = (const float*)d_in[9];
    const float* Ws1 = (const float*)d_in[10];
    const float* bs1 = (const float*)d_in[11];

    const float* Wq2 = (const float*)d_in[12];
    const float* bq2 = (const float*)d_in[13];
    const float* Wk2 = (const float*)d_in[14];
    const float* bk2 = (const float*)d_in[15];
    const float* Wv2 = (const float*)d_in[16];
    const float* bv2 = (const float*)d_in[17];
    const float* We2 = (const float*)d_in[18];
    const float* Ws2 = (const float*)d_in[19];
    const float* bs2 = (const float*)d_in[20];

    const float* Wm1 = (const float*)d_in[21];
    const float* bm1 = (const float*)d_in[22];
    const float* Wm2 = (const float*)d_in[23];
    const float* bm2 = (const float*)d_in[24];

    float* out = (float*)d_out;

    int N = in_sizes[0] / 32;
    int E = in_sizes[1] / 16;

    int edgeWarpBlocks = (E + 7) / 8;
    int nodeWarpBlocks = (N + 7) / 8;
    int scatBlocks     = ((E > N ? E : N) + 255) / 256;

    // Launch order: profiled slot (4th launch) = node_attn layer 1.
    // 1: node_linear L1 (+dst histogram; g_deg==0 by tail-zero invariant)
    node_linear_kernel<<<N, 128>>>(x, 0, Wq1, bq1, Wk1, bk1, Wv1, bv1, Ws1, bs1, We1, ei, E, N);
    // 2: prefix scan -> rowptr/cursor
    csr_scan_kernel<<<1, 1024>>>(N);
    // 3: scatter (+ea permute, +deg re-zero for next replay)
    csr_scatter_kernel<<<scatBlocks, 256>>>(ei, ea, E, N);
    // 4: attention layer 1   <-- profiled launch
    node_attn_kernel<<<nodeWarpBlocks, 256>>>(We1, 0, N);

    // ---- Layer 2 ----
    node_linear_kernel<<<N, 128>>>(nullptr, 1, Wq2, bq2, Wk2, bk2, Wv2, bv2, Ws2, bs2, We2, ei, E, N);
    node_attn_kernel<<<nodeWarpBlocks, 256>>>(We2, 1, N);

    // ---- Edge MLP ----
    mlp_pre_kernel<<<nodeWarpBlocks, 256>>>(Wm1, N);
    edge_mlp_kernel<<<edgeWarpBlocks, 256>>>(ei, ea, Wm1, bm1, Wm2, bm2, out, E);
}